// round 7
// baseline (speedup 1.0000x reference)
#include <cuda_runtime.h>
#include <math.h>

// x: (B=4, S=128, H=128, W=128) fp32 ; ada_mask: (B, S, K=21) fp32
// out[b,s,h,w] = sum_k softmax(ada_mask[b,s,:])[k] * xpad[b, s+k-10, h, w]
#define B_DIM    4
#define S_DIM    128
#define HW2_DIM  8192                  // H*W / 2  (float2 pixels per plane)
#define K_DIM    21
#define PAD      10
#define TILE_S   32                    // output rows (s) per thread
#define THREADS  128
#define WROW     44                    // duplicated weight row: 21 pairs (w,w) + pad pair
#define WIN      (TILE_S + K_DIM)      // 53 slots; <=22 live at a time (rolling)

typedef unsigned long long u64;

// Packed 2-wide fp32 FMA / ADD (Blackwell f32x2) — one instr, two fp32 lanes.
__device__ __forceinline__ u64 fma2(u64 a, u64 b, u64 c) {
    u64 d;
    asm("fma.rn.f32x2 %0, %1, %2, %3;" : "=l"(d) : "l"(a), "l"(b), "l"(c));
    return d;
}
__device__ __forceinline__ u64 add2(u64 a, u64 b) {
    u64 d;
    asm("add.rn.f32x2 %0, %1, %2;" : "=l"(d) : "l"(a), "l"(b));
    return d;
}

__global__ __launch_bounds__(THREADS, 6)
void AdaptiveMixing_28784870818046_kernel(const u64*   __restrict__ x,
                                          const float* __restrict__ ada_mask,
                                          u64*         __restrict__ out)
{
    // duplicated softmax weights: row j holds pairs (w_k, w_k), k = 0..20; pair 21 = pad
    __shared__ __align__(16) float ws[TILE_S * WROW];

    const int b  = blockIdx.z;
    const int s0 = blockIdx.y * TILE_S;
    const int p  = blockIdx.x * THREADS + threadIdx.x;   // float2-pixel idx [0, HW2)

    // ---- per-(b,s) softmax over K=21, stored duplicated ----
    if (threadIdx.x < TILE_S) {
        const int s = s0 + threadIdx.x;
        const float* m = ada_mask + ((size_t)b * S_DIM + s) * K_DIM;
        float mv[K_DIM];
        float mx = -3.402823466e+38f;
        #pragma unroll
        for (int k = 0; k < K_DIM; ++k) { mv[k] = m[k]; mx = fmaxf(mx, mv[k]); }
        float sum = 0.f;
        #pragma unroll
        for (int k = 0; k < K_DIM; ++k) { mv[k] = expf(mv[k] - mx); sum += mv[k]; }
        const float inv = 1.0f / sum;
        float* row = ws + threadIdx.x * WROW;
        #pragma unroll
        for (int k = 0; k < K_DIM; ++k) {
            const float w = mv[k] * inv;
            row[2 * k]     = w;
            row[2 * k + 1] = w;
        }
        row[42] = 0.f;   // pad pair
        row[43] = 0.f;
    }
    __syncthreads();

    const u64* xb = x + (size_t)b * S_DIM * HW2_DIM + p;
    u64*       ob = out + ((size_t)b * S_DIM + s0) * HW2_DIM + p;

    // ---- rolling 21-plane float2 window; row j consumes win[j .. j+20] only ----
    u64 win[WIN];

    // preload planes 0..20  (plane i holds x[s0-10+i]; out of range -> 0)
    #pragma unroll
    for (int i = 0; i < K_DIM; ++i) {
        const int s = s0 - PAD + i;
        win[i] = (s >= 0 && s < S_DIM) ? xb[(size_t)s * HW2_DIM] : 0ULL;
    }

    #pragma unroll
    for (int j = 0; j < TILE_S; ++j) {
        // prefetch plane j+21: first consumed as the LAST term of row j+1
        if (j + 1 < TILE_S) {
            const int s = s0 - PAD + j + K_DIM;      // s = s0 + j + 11 (only top clip)
            win[j + K_DIM] = (s < S_DIM) ? xb[(size_t)s * HW2_DIM] : 0ULL;
        }

        const float* row = ws + j * WROW;
        u64 a = 0ULL, c = 0ULL;                      // 2 accumulation chains

        #pragma unroll
        for (int q = 0; q < 10; ++q) {
            const ulonglong2 wp = reinterpret_cast<const ulonglong2*>(row)[q];
            a = fma2(wp.x, win[j + 2 * q],     a);
            c = fma2(wp.y, win[j + 2 * q + 1], c);
        }
        // k = 20 singleton (duplicated pair at float-offset 40)
        a = fma2(reinterpret_cast<const u64*>(row)[20], win[j + 20], a);

        ob[(size_t)j * HW2_DIM] = add2(a, c);
    }
}

extern "C" void kernel_launch(void* const* d_in, const int* in_sizes, int n_in,
                              void* d_out, int out_size)
{
    const u64* x          = (const u64*)d_in[0];     // (4,128,128,128) fp32 as float2
    const float* ada_mask = (const float*)d_in[1];   // (4,128,21) fp32
    u64* out              = (u64*)d_out;

    dim3 grid(HW2_DIM / THREADS,   // 64 pixel-blocks
              S_DIM / TILE_S,      // 4 s-tiles
              B_DIM);              // 4 batches
    AdaptiveMixing_28784870818046_kernel<<<grid, THREADS>>>(x, ada_mask, out);
}

// round 8
// speedup vs baseline: 1.2142x; 1.2142x over previous
#include <cuda_runtime.h>
#include <math.h>

// x: (B=4, S=128, H=128, W=128) fp32 ; ada_mask: (B, S, K=21) fp32
// out[b,s,h,w] = sum_k softmax(ada_mask[b,s,:])[k] * xpad[b, s+k-10, h, w]
#define B_DIM    4
#define S_DIM    128
#define HW2_DIM  8192                  // H*W / 2  (float2 pixels per plane)
#define K_DIM    21
#define PAD      10
#define TILE_S   32                    // output rows (s) per thread
#define THREADS  128
#define WROW     44                    // duplicated weight row: 21 pairs (w,w) + pad pair
#define WIN      (TILE_S + K_DIM)      // 53 planes, ALL loaded upfront (batched MLP)

typedef unsigned long long u64;

// Packed 2-wide fp32 FMA / ADD (Blackwell f32x2) — one instr, two fp32 lanes.
__device__ __forceinline__ u64 fma2(u64 a, u64 b, u64 c) {
    u64 d;
    asm("fma.rn.f32x2 %0, %1, %2, %3;" : "=l"(d) : "l"(a), "l"(b), "l"(c));
    return d;
}
__device__ __forceinline__ u64 add2(u64 a, u64 b) {
    u64 d;
    asm("add.rn.f32x2 %0, %1, %2;" : "=l"(d) : "l"(a), "l"(b));
    return d;
}

__global__ __launch_bounds__(THREADS, 4)
void AdaptiveMixing_28784870818046_kernel(const u64*   __restrict__ x,
                                          const float* __restrict__ ada_mask,
                                          u64*         __restrict__ out)
{
    // duplicated softmax weights: row j holds pairs (w_k, w_k), k = 0..20; pair 21 = pad
    __shared__ __align__(16) float ws[TILE_S * WROW];

    const int b  = blockIdx.z;
    const int s0 = blockIdx.y * TILE_S;
    const int p  = blockIdx.x * THREADS + threadIdx.x;   // float2-pixel idx [0, HW2)

    // ---- per-(b,s) softmax over K=21, stored duplicated ----
    if (threadIdx.x < TILE_S) {
        const int s = s0 + threadIdx.x;
        const float* m = ada_mask + ((size_t)b * S_DIM + s) * K_DIM;
        float mv[K_DIM];
        float mx = -3.402823466e+38f;
        #pragma unroll
        for (int k = 0; k < K_DIM; ++k) { mv[k] = m[k]; mx = fmaxf(mx, mv[k]); }
        float sum = 0.f;
        #pragma unroll
        for (int k = 0; k < K_DIM; ++k) { mv[k] = expf(mv[k] - mx); sum += mv[k]; }
        const float inv = 1.0f / sum;
        float* row = ws + threadIdx.x * WROW;
        #pragma unroll
        for (int k = 0; k < K_DIM; ++k) {
            const float w = mv[k] * inv;
            row[2 * k]     = w;
            row[2 * k + 1] = w;
        }
        row[42] = 0.f;   // pad pair
        row[43] = 0.f;
    }
    __syncthreads();

    const u64* xb = x + (size_t)b * S_DIM * HW2_DIM + p;
    u64*       ob = out + ((size_t)b * S_DIM + s0) * HW2_DIM + p;

    // ---- load ALL 53 planes upfront: one batched latency, max MLP ----
    // (all values genuinely live until their last consuming row, so ptxas
    //  cannot collapse the batch back into per-row loads)
    u64 win[WIN];
    #pragma unroll
    for (int i = 0; i < WIN; ++i) {
        const int s = s0 - PAD + i;
        win[i] = (s >= 0 && s < S_DIM) ? xb[(size_t)s * HW2_DIM] : 0ULL;
    }

    // ---- 32 compute-only rows: 11 LDS + 21 fma2 + 1 add2 + 1 STG each ----
    #pragma unroll
    for (int j = 0; j < TILE_S; ++j) {
        const float* row = ws + j * WROW;
        u64 a = 0ULL, c = 0ULL;                      // 2 accumulation chains

        #pragma unroll
        for (int q = 0; q < 10; ++q) {
            const ulonglong2 wp = reinterpret_cast<const ulonglong2*>(row)[q];
            a = fma2(wp.x, win[j + 2 * q],     a);
            c = fma2(wp.y, win[j + 2 * q + 1], c);
        }
        // k = 20 singleton (duplicated pair at float-offset 40)
        a = fma2(reinterpret_cast<const u64*>(row)[20], win[j + 20], a);

        ob[(size_t)j * HW2_DIM] = add2(a, c);
    }
}

extern "C" void kernel_launch(void* const* d_in, const int* in_sizes, int n_in,
                              void* d_out, int out_size)
{
    const u64* x          = (const u64*)d_in[0];     // (4,128,128,128) fp32 as float2
    const float* ada_mask = (const float*)d_in[1];   // (4,128,21) fp32
    u64* out              = (u64*)d_out;

    dim3 grid(HW2_DIM / THREADS,   // 64 pixel-blocks
              S_DIM / TILE_S,      // 4 s-tiles
              B_DIM);              // 4 batches
    AdaptiveMixing_28784870818046_kernel<<<grid, THREADS>>>(x, ada_mask, out);
}

// round 9
// speedup vs baseline: 1.3662x; 1.1252x over previous
#include <cuda_runtime.h>
#include <math.h>

// x: (B=4, S=128, H=128, W=128) fp32 ; ada_mask: (B, S, K=21) fp32
// out[b,s,h,w] = sum_k softmax(ada_mask[b,s,:])[k] * xpad[b, s+k-10, h, w]
#define B_DIM    4
#define S_DIM    128
#define HW2_DIM  8192                  // H*W / 2 (float2 pixels per plane)
#define K_DIM    21
#define PAD      10
#define TILE_S   16                    // output rows (s) per thread
#define THREADS  128
#define WROW     22                    // weight row: 21 weights + 1 pad float (align)
#define WIN      (TILE_S + K_DIM - 1)  // 36 input planes per tile

__global__ __launch_bounds__(THREADS, 5)
void AdaptiveMixing_28784870818046_kernel(const float2* __restrict__ x,
                                          const float*  __restrict__ ada_mask,
                                          float2* __restrict__ out)
{
    __shared__ __align__(16) float ws[TILE_S * WROW + 2];  // +2: float4 reads stay in-bounds

    const int b  = blockIdx.z;
    const int s0 = blockIdx.y * TILE_S;
    const int p  = blockIdx.x * THREADS + threadIdx.x;   // float2-pixel idx [0, HW2)

    // ---- per-(b,s) softmax over K=21 for rows s0..s0+15 ----
    if (threadIdx.x < TILE_S) {
        const int s = s0 + threadIdx.x;
        const float* m = ada_mask + ((size_t)b * S_DIM + s) * K_DIM;
        float mv[K_DIM];
        float mx = -3.402823466e+38f;
        #pragma unroll
        for (int k = 0; k < K_DIM; ++k) { mv[k] = m[k]; mx = fmaxf(mx, mv[k]); }
        float sum = 0.f;
        #pragma unroll
        for (int k = 0; k < K_DIM; ++k) { mv[k] = expf(mv[k] - mx); sum += mv[k]; }
        const float inv = 1.0f / sum;
        float* row = ws + threadIdx.x * WROW;
        #pragma unroll
        for (int k = 0; k < K_DIM; ++k) row[k] = mv[k] * inv;
        row[21] = 0.f;
    }
    __syncthreads();

    // ---- upfront batched load of the full 36-plane float2 window ----
    float2 win[WIN];
    const float2* xb = x + (size_t)b * S_DIM * HW2_DIM + p;
    #pragma unroll
    for (int i = 0; i < WIN; ++i) {
        const int s = s0 - PAD + i;
        win[i] = (s >= 0 && s < S_DIM) ? xb[(size_t)s * HW2_DIM]
                                       : make_float2(0.f, 0.f);
    }

    // ---- 16 compute-only rows: 21-wide dot on a float2 pixel pair ----
    float2* ob = out + ((size_t)b * S_DIM + s0) * HW2_DIM + p;
    #pragma unroll
    for (int j = 0; j < TILE_S; ++j) {
        const float* row = ws + j * WROW;
        float a0x = 0.f, a0y = 0.f, a1x = 0.f, a1y = 0.f;  // 2 chains x 2 pixels
        #pragma unroll
        for (int q = 0; q < 5; ++q) {                      // k = 0..19 via float4 LDS
            const float4 w4 = reinterpret_cast<const float4*>(row)[q];
            const float2 v0 = win[j + 4*q + 0];
            const float2 v1 = win[j + 4*q + 1];
            const float2 v2 = win[j + 4*q + 2];
            const float2 v3 = win[j + 4*q + 3];
            a0x = fmaf(w4.x, v0.x, a0x);  a0y = fmaf(w4.x, v0.y, a0y);
            a1x = fmaf(w4.y, v1.x, a1x);  a1y = fmaf(w4.y, v1.y, a1y);
            a0x = fmaf(w4.z, v2.x, a0x);  a0y = fmaf(w4.z, v2.y, a0y);
            a1x = fmaf(w4.w, v3.x, a1x);  a1y = fmaf(w4.w, v3.y, a1y);
        }
        {                                                  // k = 20 singleton
            const float w20 = row[20];
            const float2 v = win[j + 20];
            a0x = fmaf(w20, v.x, a0x);    a0y = fmaf(w20, v.y, a0y);
        }
        float2 r;
        r.x = a0x + a1x;
        r.y = a0y + a1y;
        ob[(size_t)j * HW2_DIM] = r;
    }
}

extern "C" void kernel_launch(void* const* d_in, const int* in_sizes, int n_in,
                              void* d_out, int out_size)
{
    const float2* x       = (const float2*)d_in[0];   // (4,128,128,128) fp32 as float2
    const float* ada_mask = (const float*)d_in[1];    // (4,128,21) fp32
    float2* out           = (float2*)d_out;

    dim3 grid(HW2_DIM / THREADS,   // 64 pixel-blocks
              S_DIM / TILE_S,      // 8 s-tiles
              B_DIM);              // 4 batches
    AdaptiveMixing_28784870818046_kernel<<<grid, THREADS>>>(x, ada_mask, out);
}